// round 5
// baseline (speedup 1.0000x reference)
#include <cuda_runtime.h>
#include <math.h>

// Problem constants
#define BB 4
#define HH 200
#define WW 176
#define HW (HH*WW)         // 35200
#define FA 10
#define NF 5
#define NFR (BB*NF)        // 20 (b,frame) pairs
#define NPF (HW*2)         // 70400 elements per frame
#define EPSV 1e-6f
#define NBIN 4096
#define CAP 6144

// ---- scratch (device globals; no allocations allowed) ----
__device__ float  g_vbuf[BB*NF*NPF];     // per-frame masked psm logits (x), 5.6MB
__device__ int    g_hist[NFR*NBIN];      // 12-bit-prefix histograms of x keys
__device__ int    g_pcnt[NFR];           // positives per (b,frame)
__device__ double g_clspos, g_huber, g_num;

// monotonic float<->uint key mapping (ascending)
__device__ __forceinline__ unsigned kmap(float x){
    unsigned u = __float_as_uint(x);
    return (u & 0x80000000u) ? ~u : (u | 0x80000000u);
}
__device__ __forceinline__ float kunmap(unsigned m){
    unsigned u = (m & 0x80000000u) ? (m & 0x7FFFFFFFu) : ~m;
    return __uint_as_float(u);
}
// neg-class loss value from raw psm logit (monotone non-decreasing in x):
// every stage (expf, 1+, rcp, 1-, +eps, logf, negate) is monotone in float,
// so top-k by x-key == top-k by v-value (sum is tie-invariant).
__device__ __forceinline__ float vneg(float x){
    float pp = 1.0f/(1.0f + expf(-x));
    return -logf(1.0f - pp + EPSV);
}
__device__ __forceinline__ double wredd(double v){
    #pragma unroll
    for (int o=16;o;o>>=1) v += __shfl_down_sync(0xffffffffu, v, o);
    return v;
}

// ---------------- zero scratch ----------------
__global__ void k_zero(){
    int i = blockIdx.x*blockDim.x + threadIdx.x;
    if (i < NFR*NBIN/4) ((int4*)g_hist)[i] = make_int4(0,0,0,0);
    if (i < NFR) g_pcnt[i]=0;
    if (i == 0){ g_clspos=0.0; g_huber=0.0; g_num=0.0; }
}

// ---------------- main pass ----------------
// one thread per spatial position (b, h*W+w); handles all 10 anchors there.
// NO transcendentals except in the rare (~0.5%) positive branch.
__global__ void __launch_bounds__(256) k_main(
    const float* __restrict__ rm,  const float* __restrict__ psm,
    const float* __restrict__ pos, const float* __restrict__ neg,
    const float* __restrict__ tgt)
{
    __shared__ float s_pos[2560], s_neg[2560];
    __shared__ int s_cnt[NF];
    __shared__ double sA[8], sB[8];
    int b = blockIdx.y;
    int tid = threadIdx.x;
    int p0 = blockIdx.x*256;
    int npos = HW - p0; if (npos > 256) npos = 256;   // HW%256==128, stays /4
    int nq = npos*FA/4;
    const float4* sp = (const float4*)(pos + ((size_t)b*HW + p0)*FA);
    const float4* sn = (const float4*)(neg + ((size_t)b*HW + p0)*FA);
    for (int i=tid; i<nq; i+=256){
        ((float4*)s_pos)[i] = sp[i];
        ((float4*)s_neg)[i] = sn[i];
    }
    if (tid < NF) s_cnt[tid] = 0;
    __syncthreads();

    int p = p0 + tid;
    double l_cp = 0.0, l_hb = 0.0;
    if (tid < npos){
        float w[FA];
        #pragma unroll
        for (int a=0;a<FA;a++){
            float x = psm[((size_t)(b*FA + a))*HW + p];
            bool nz = (s_neg[tid*FA + a] != 0.0f);
            if (nz)
                atomicAdd(&g_hist[((b*NF + (a>>1)) << 12) + (int)(kmap(x) >> 20)], 1);
            w[a] = nz ? x : __int_as_float(0x7FC00000);  // NaN = masked out
            if (s_pos[tid*FA + a] != 0.0f){
                atomicAdd(&s_cnt[a>>1], 1);
                float pp = 1.0f/(1.0f + expf(-x));
                l_cp -= (double)logf(pp + EPSV);
                const float* tp = tgt + (((size_t)b*HW + p)*(FA*7) + a*7);
                const float* rp = rm  + ((size_t)(b*FA*7) + a*7)*HW + p;
                #pragma unroll
                for (int j=0;j<7;j++){
                    float d = fabsf(rp[(size_t)j*HW] - tp[j]);
                    l_hb += (d < 1.0f) ? (double)(0.5f*d*d) : (double)(d - 0.5f);
                }
            }
        }
        #pragma unroll
        for (int f=0; f<NF; f++){
            float2 w2; w2.x = w[2*f]; w2.y = w[2*f+1];
            *(float2*)(g_vbuf + ((size_t)(b*NF+f))*NPF + (size_t)p*2) = w2;
        }
    }
    // block-reduce the two double sums
    double r1 = wredd(l_cp), r2 = wredd(l_hb);
    int lane = tid & 31, wd = tid >> 5;
    if (lane==0){ sA[wd]=r1; sB[wd]=r2; }
    __syncthreads();
    if (wd==0){
        double a = (lane<8)? sA[lane] : 0.0; a = wredd(a);
        double c = (lane<8)? sB[lane] : 0.0; c = wredd(c);
        if (lane==0){
            if (a != 0.0) atomicAdd(&g_clspos, a);
            if (c != 0.0) atomicAdd(&g_huber, c);
        }
    }
    if (tid < NF && s_cnt[tid]) atomicAdd(&g_pcnt[b*NF + tid], s_cnt[tid]);
}

// hierarchical suffix scan over shared hist[4096]; thread 0 writes (*oP,*oR).
__device__ __forceinline__ void scan_pick(int* hist, int* Sc, int* Sw,
                                          int k, int* oP, int* oR, int tid)
{
    int c = tid;                       // blockDim.x == 1024
    int s4 = hist[4*c] + hist[4*c+1] + hist[4*c+2] + hist[4*c+3];
    Sc[c] = s4;
    int ws = s4;
    #pragma unroll
    for (int o=16;o;o>>=1) ws += __shfl_down_sync(0xffffffffu, ws, o);
    if ((tid & 31) == 0) Sw[tid >> 5] = ws;
    __syncthreads();
    if (tid == 0){
        int cum = 0, s = 31;
        while (s > 0 && cum + Sw[s] < k){ cum += Sw[s]; s--; }
        int cc = s*32 + 31;
        while (cc > s*32 && cum + Sc[cc] < k){ cum += Sc[cc]; cc--; }
        int bb = cc*4 + 3;
        while (bb > cc*4 && cum + hist[bb] < k){ cum += hist[bb]; bb--; }
        *oP = bb; *oR = k - cum;
    }
    __syncthreads();
}

// ---------------- per-frame exact top-k sum (keys = psm logits) ----------------
__global__ void __launch_bounds__(1024) k_select(){
    __shared__ int hist[NBIN];
    __shared__ int Sc[1024];
    __shared__ int Sw[32];
    __shared__ int sP, sR, sP2, sR2, s_n, s_m, s_cgt;
    __shared__ unsigned s_tk;
    __shared__ float cand[CAP];
    __shared__ float cand2[256];
    __shared__ double sD[32];

    int f = blockIdx.x, tid = threadIdx.x;
    for (int i=tid; i<NBIN; i+=1024) hist[i] = g_hist[(f<<12) + i];
    if (tid == 0){ s_n = 0; s_m = 0; s_cgt = 0; s_tk = 0u; }
    __syncthreads();

    int k = 3*(g_pcnt[f] + 1);               // floor(3*(cnt+1)) exactly
    scan_pick(hist, Sc, Sw, k, &sP, &sR, tid);
    int P = sP;

    // pass over plane: sum v(x) above-bin, collect in-bin candidate x's
    double acc = 0.0;
    const float4* vp = (const float4*)(g_vbuf + (size_t)f*NPF);
    for (int i=tid; i<NPF/4; i+=1024){
        float4 q = vp[i];
        float xv[4] = {q.x, q.y, q.z, q.w};
        #pragma unroll
        for (int j=0;j<4;j++){
            float x = xv[j];
            if (x == x){                       // not NaN => neg==1 anchor
                int t = (int)(kmap(x) >> 20);
                if (t > P) acc += (double)vneg(x);
                else if (t == P){
                    int id = atomicAdd(&s_n, 1);
                    if (id < CAP) cand[id] = x;
                }
            }
        }
    }
    __syncthreads();
    int n = s_n; if (n > CAP) n = CAP;

    // level-2 refinement on candidate keys: next 12 bits
    for (int i=tid; i<NBIN; i+=1024) hist[i] = 0;
    __syncthreads();
    for (int i=tid; i<n; i+=1024)
        atomicAdd(&hist[(kmap(cand[i]) >> 8) & 0xFFF], 1);
    __syncthreads();
    scan_pick(hist, Sc, Sw, sR, &sP2, &sR2, tid);
    int P2 = sP2;

    for (int i=tid; i<n; i+=1024){
        float x = cand[i];
        int t = (int)((kmap(x) >> 8) & 0xFFF);
        if (t > P2) acc += (double)vneg(x);
        else if (t == P2){
            int id = atomicAdd(&s_m, 1);
            if (id < 256) cand2[id] = x;
        }
    }
    __syncthreads();
    int m = s_m; if (m > 256) m = 256;
    int r2 = sR2;

    if (m > 0){
        // exact tie-aware finish on tiny candidate set
        for (int i=tid; i<m; i+=1024){
            unsigned ki = kmap(cand2[i]);
            int cgt = 0, ceq = 0;
            for (int j=0;j<m;j++){
                unsigned kj = kmap(cand2[j]);
                cgt += (kj > ki); ceq += (kj == ki);
            }
            if (cgt < r2 && r2 <= cgt + ceq) s_tk = ki;  // benign same-value race
        }
        __syncthreads();
        unsigned tk = s_tk;
        int cl = 0;
        for (int i=tid; i<m; i+=1024){
            unsigned ki = kmap(cand2[i]);
            if (ki > tk){ acc += (double)vneg(cand2[i]); cl++; }
        }
        if (cl) atomicAdd(&s_cgt, cl);
        __syncthreads();
        if (tid == 0) acc += (double)(r2 - s_cgt) * (double)vneg(kunmap(tk));
    }

    // block reduce acc (32 warps) -> g_num
    double r = wredd(acc);
    if ((tid & 31) == 0) sD[tid >> 5] = r;
    __syncthreads();
    if (tid < 32){
        double a = sD[tid];
        a = wredd(a);
        if (tid == 0) atomicAdd(&g_num, a);
    }
}

// ---------------- finalize 4 scalars (one warp, parallel loads) ----------------
__global__ void k_final(float* out){
    int tid = threadIdx.x;
    int c = (tid < NFR) ? g_pcnt[tid] : 0;
    int cnt = c, den = (tid < NFR) ? 3*(c+1) : 0;
    #pragma unroll
    for (int o=16;o;o>>=1){
        cnt += __shfl_down_sync(0xffffffffu, cnt, o);
        den += __shfl_down_sync(0xffffffffu, den, o);
    }
    if (tid == 0){
        double ps   = (double)cnt + 1e-6;
        double clsp = 1.5 * g_clspos / ps;        // ALPHA
        double reg  = 2.0 * g_huber  / ps;        // GAMMA
        double clsn = 1.0 * g_num / ((double)den + 1e-6); // BETA
        out[0] = (float)(clsp + clsn);  // conf_loss
        out[1] = (float)reg;            // reg_loss
        out[2] = (float)clsp;           // cls_pos_loss
        out[3] = (float)clsn;           // cls_neg_loss
    }
}

extern "C" void kernel_launch(void* const* d_in, const int* in_sizes, int n_in,
                              void* d_out, int out_size)
{
    const float* rm  = (const float*)d_in[0];
    const float* psm = (const float*)d_in[1];
    const float* pos = (const float*)d_in[2];
    const float* neg = (const float*)d_in[3];
    const float* tgt = (const float*)d_in[4];
    float* out = (float*)d_out;

    k_zero<<<(NFR*NBIN/4 + 255)/256, 256>>>();
    dim3 g1((HW + 255)/256, BB);
    k_main<<<g1, 256>>>(rm, psm, pos, neg, tgt);
    k_select<<<NFR, 1024>>>();
    k_final<<<1, 32>>>(out);
}

// round 6
// speedup vs baseline: 1.0291x; 1.0291x over previous
#include <cuda_runtime.h>
#include <math.h>

// Problem constants
#define BB 4
#define HH 200
#define WW 176
#define HW (HH*WW)         // 35200
#define FA 10
#define NF 5
#define NFR (BB*NF)        // 20 (b,frame) pairs
#define NPF (HW*2)         // 70400 elements per frame
#define EPSV 1e-6f
#define NBIN 4096
#define CAP 6144

// ---- scratch (device globals; zero-initialized at load; self-cleaning) ----
__device__ float  g_vbuf[BB*NF*NPF];     // per-frame masked psm logits (x), 5.6MB
__device__ int    g_hist[NFR*NBIN];      // 12-bit-prefix histograms of x keys
__device__ int    g_pcnt[NFR];           // positives per (b,frame)
__device__ double g_clspos, g_huber, g_num;
__device__ int    g_done;                // last-block counter

// monotonic float<->uint key mapping (ascending)
__device__ __forceinline__ unsigned kmap(float x){
    unsigned u = __float_as_uint(x);
    return (u & 0x80000000u) ? ~u : (u | 0x80000000u);
}
__device__ __forceinline__ float kunmap(unsigned m){
    unsigned u = (m & 0x80000000u) ? (m & 0x7FFFFFFFu) : ~m;
    return __uint_as_float(u);
}
// neg-class loss from raw logit (monotone non-decreasing in x => top-k by x == top-k by v)
__device__ __forceinline__ float vneg(float x){
    float pp = 1.0f/(1.0f + expf(-x));
    return -logf(1.0f - pp + EPSV);
}
__device__ __forceinline__ double wredd(double v){
    #pragma unroll
    for (int o=16;o;o>>=1) v += __shfl_down_sync(0xffffffffu, v, o);
    return v;
}

// ---------------- main pass ----------------
// one thread per spatial position (b, h*W+w); handles all 10 anchors there.
// assumes g_hist/g_pcnt/g_clspos/g_huber zeroed (load-time init, then self-cleaned).
__global__ void __launch_bounds__(256) k_main(
    const float* __restrict__ rm,  const float* __restrict__ psm,
    const float* __restrict__ pos, const float* __restrict__ neg,
    const float* __restrict__ tgt)
{
    __shared__ float s_pos[2560], s_neg[2560];
    __shared__ int s_cnt[NF];
    __shared__ double sA[8], sB[8];
    int b = blockIdx.y;
    int tid = threadIdx.x;
    int p0 = blockIdx.x*256;
    int npos = HW - p0; if (npos > 256) npos = 256;   // HW%256==128, stays /4
    int nq = npos*FA/4;
    const float4* sp = (const float4*)(pos + ((size_t)b*HW + p0)*FA);
    const float4* sn = (const float4*)(neg + ((size_t)b*HW + p0)*FA);
    for (int i=tid; i<nq; i+=256){
        ((float4*)s_pos)[i] = sp[i];
        ((float4*)s_neg)[i] = sn[i];
    }
    if (tid < NF) s_cnt[tid] = 0;
    __syncthreads();

    int p = p0 + tid;
    double l_cp = 0.0, l_hb = 0.0;
    if (tid < npos){
        float w[FA];
        #pragma unroll
        for (int a=0;a<FA;a++){
            float x = psm[((size_t)(b*FA + a))*HW + p];
            bool nz = (s_neg[tid*FA + a] != 0.0f);
            if (nz)
                atomicAdd(&g_hist[((b*NF + (a>>1)) << 12) + (int)(kmap(x) >> 20)], 1);
            w[a] = nz ? x : __int_as_float(0x7FC00000);  // NaN = masked out
            if (s_pos[tid*FA + a] != 0.0f){
                atomicAdd(&s_cnt[a>>1], 1);
                float pp = 1.0f/(1.0f + expf(-x));
                l_cp -= (double)logf(pp + EPSV);
                const float* tp = tgt + (((size_t)b*HW + p)*(FA*7) + a*7);
                const float* rp = rm  + ((size_t)(b*FA*7) + a*7)*HW + p;
                #pragma unroll
                for (int j=0;j<7;j++){
                    float d = fabsf(rp[(size_t)j*HW] - tp[j]);
                    l_hb += (d < 1.0f) ? (double)(0.5f*d*d) : (double)(d - 0.5f);
                }
            }
        }
        #pragma unroll
        for (int f=0; f<NF; f++){
            float2 w2; w2.x = w[2*f]; w2.y = w[2*f+1];
            *(float2*)(g_vbuf + ((size_t)(b*NF+f))*NPF + (size_t)p*2) = w2;
        }
    }
    // block-reduce the two double sums
    double r1 = wredd(l_cp), r2 = wredd(l_hb);
    int lane = tid & 31, wd = tid >> 5;
    if (lane==0){ sA[wd]=r1; sB[wd]=r2; }
    __syncthreads();
    if (wd==0){
        double a = (lane<8)? sA[lane] : 0.0; a = wredd(a);
        double c = (lane<8)? sB[lane] : 0.0; c = wredd(c);
        if (lane==0){
            if (a != 0.0) atomicAdd(&g_clspos, a);
            if (c != 0.0) atomicAdd(&g_huber, c);
        }
    }
    if (tid < NF && s_cnt[tid]) atomicAdd(&g_pcnt[b*NF + tid], s_cnt[tid]);
}

// hierarchical suffix scan over shared hist[4096]; thread 0 writes (*oP,*oR).
__device__ __forceinline__ void scan_pick(int* hist, int* Sc, int* Sw,
                                          int k, int* oP, int* oR, int tid)
{
    int c = tid;                       // blockDim.x == 1024
    int s4 = hist[4*c] + hist[4*c+1] + hist[4*c+2] + hist[4*c+3];
    Sc[c] = s4;
    int ws = s4;
    #pragma unroll
    for (int o=16;o;o>>=1) ws += __shfl_down_sync(0xffffffffu, ws, o);
    if ((tid & 31) == 0) Sw[tid >> 5] = ws;
    __syncthreads();
    if (tid == 0){
        int cum = 0, s = 31;
        while (s > 0 && cum + Sw[s] < k){ cum += Sw[s]; s--; }
        int cc = s*32 + 31;
        while (cc > s*32 && cum + Sc[cc] < k){ cum += Sc[cc]; cc--; }
        int bb = cc*4 + 3;
        while (bb > cc*4 && cum + hist[bb] < k){ cum += hist[bb]; bb--; }
        *oP = bb; *oR = k - cum;
    }
    __syncthreads();
}

// ---------------- per-frame exact top-k sum + fused finalize ----------------
__global__ void __launch_bounds__(1024) k_sel(float* __restrict__ out){
    __shared__ int hist[NBIN];
    __shared__ int Sc[1024];
    __shared__ int Sw[32];
    __shared__ int sP, sR, sP2, sR2, s_n, s_m, s_cgt, s_last;
    __shared__ unsigned s_tk;
    __shared__ float cand[CAP];
    __shared__ float cand2[256];
    __shared__ double sD[32];

    int f = blockIdx.x, tid = threadIdx.x;
    for (int i=tid; i<NBIN; i+=1024) hist[i] = g_hist[(f<<12) + i];
    if (tid == 0){ s_n = 0; s_m = 0; s_cgt = 0; s_tk = 0u; }
    __syncthreads();
    // self-clean: re-zero this frame's hist slice for the next invocation
    for (int i=tid; i<NBIN/4; i+=1024)
        ((int4*)(g_hist + (f<<12)))[i] = make_int4(0,0,0,0);

    int k = 3*(g_pcnt[f] + 1);               // floor(3*(cnt+1)) exactly
    scan_pick(hist, Sc, Sw, k, &sP, &sR, tid);
    int P = sP;

    // pass over plane: sum v(x) above-bin, collect in-bin candidate x's
    double acc = 0.0;
    const float4* vp = (const float4*)(g_vbuf + (size_t)f*NPF);
    for (int i=tid; i<NPF/4; i+=1024){
        float4 q = vp[i];
        float xv[4] = {q.x, q.y, q.z, q.w};
        #pragma unroll
        for (int j=0;j<4;j++){
            float x = xv[j];
            if (x == x){                       // not NaN => neg==1 anchor
                int t = (int)(kmap(x) >> 20);
                if (t > P) acc += (double)vneg(x);
                else if (t == P){
                    int id = atomicAdd(&s_n, 1);
                    if (id < CAP) cand[id] = x;
                }
            }
        }
    }
    __syncthreads();
    int n = s_n; if (n > CAP) n = CAP;

    // level-2 refinement on candidate keys: next 12 bits
    for (int i=tid; i<NBIN; i+=1024) hist[i] = 0;
    __syncthreads();
    for (int i=tid; i<n; i+=1024)
        atomicAdd(&hist[(kmap(cand[i]) >> 8) & 0xFFF], 1);
    __syncthreads();
    scan_pick(hist, Sc, Sw, sR, &sP2, &sR2, tid);
    int P2 = sP2;

    for (int i=tid; i<n; i+=1024){
        float x = cand[i];
        int t = (int)((kmap(x) >> 8) & 0xFFF);
        if (t > P2) acc += (double)vneg(x);
        else if (t == P2){
            int id = atomicAdd(&s_m, 1);
            if (id < 256) cand2[id] = x;
        }
    }
    __syncthreads();
    int m = s_m; if (m > 256) m = 256;
    int r2 = sR2;

    if (m > 0){
        // exact tie-aware finish on tiny candidate set
        for (int i=tid; i<m; i+=1024){
            unsigned ki = kmap(cand2[i]);
            int cgt = 0, ceq = 0;
            for (int j=0;j<m;j++){
                unsigned kj = kmap(cand2[j]);
                cgt += (kj > ki); ceq += (kj == ki);
            }
            if (cgt < r2 && r2 <= cgt + ceq) s_tk = ki;  // benign same-value race
        }
        __syncthreads();
        unsigned tk = s_tk;
        int cl = 0;
        for (int i=tid; i<m; i+=1024){
            unsigned ki = kmap(cand2[i]);
            if (ki > tk){ acc += (double)vneg(cand2[i]); cl++; }
        }
        if (cl) atomicAdd(&s_cgt, cl);
        __syncthreads();
        if (tid == 0) acc += (double)(r2 - s_cgt) * (double)vneg(kunmap(tk));
    }

    // block reduce acc -> g_num, then last-block finalize
    double r = wredd(acc);
    if ((tid & 31) == 0) sD[tid >> 5] = r;
    __syncthreads();
    if (tid < 32){
        double a = sD[tid];
        a = wredd(a);
        if (tid == 0){
            atomicAdd(&g_num, a);
            __threadfence();                       // g_num visible before counter
            int old = atomicAdd(&g_done, 1);
            s_last = (old == NFR-1);
        }
    }
    __syncthreads();
    if (s_last && tid < 32){
        __threadfence();                           // acquire all blocks' writes
        int c = (tid < NFR) ? g_pcnt[tid] : 0;
        int cnt = c, den = (tid < NFR) ? 3*(c+1) : 0;
        #pragma unroll
        for (int o=16;o;o>>=1){
            cnt += __shfl_down_sync(0xffffffffu, cnt, o);
            den += __shfl_down_sync(0xffffffffu, den, o);
        }
        if (tid == 0){
            double num  = atomicAdd(&g_num, 0.0);  // L2 read
            double ps   = (double)cnt + 1e-6;
            double clsp = 1.5 * g_clspos / ps;        // ALPHA
            double reg  = 2.0 * g_huber  / ps;        // GAMMA
            double clsn = 1.0 * num / ((double)den + 1e-6); // BETA
            out[0] = (float)(clsp + clsn);  // conf_loss
            out[1] = (float)reg;            // reg_loss
            out[2] = (float)clsp;           // cls_pos_loss
            out[3] = (float)clsn;           // cls_neg_loss
            // self-clean scalars for next invocation
            g_clspos = 0.0; g_huber = 0.0; g_num = 0.0; g_done = 0;
        }
        if (tid < NFR) g_pcnt[tid] = 0;
    }
}

extern "C" void kernel_launch(void* const* d_in, const int* in_sizes, int n_in,
                              void* d_out, int out_size)
{
    const float* rm  = (const float*)d_in[0];
    const float* psm = (const float*)d_in[1];
    const float* pos = (const float*)d_in[2];
    const float* neg = (const float*)d_in[3];
    const float* tgt = (const float*)d_in[4];
    float* out = (float*)d_out;

    dim3 g1((HW + 255)/256, BB);
    k_main<<<g1, 256>>>(rm, psm, pos, neg, tgt);
    k_sel<<<NFR, 1024>>>(out);
}